// round 1
// baseline (speedup 1.0000x reference)
#include <cuda_runtime.h>
#include <math.h>

// Problem constants (fixed shapes)
#define NE      800000
#define NNODES  50000
#define F       64
#define ZD      192
#define HID     14
#define NT      128     // combined outputs (f || s)
#define MT      64      // edges per tile in K1
#define ZR_STRIDE 196   // 192 + 4 pad (keeps float4 alignment: 196*4 % 16 == 0)

// Scratch: combined transposed weights Wc[k][o], o<64 -> lin_f, o>=64 -> lin_s
__device__ float g_wc[ZD * NT];

// ---------------------------------------------------------------------------
// K0: init atom_out = atom_fea; build g_wc (k-major combined weights)
// ---------------------------------------------------------------------------
__global__ void k0_prep(const float* __restrict__ atom,
                        const float* __restrict__ wf,
                        const float* __restrict__ ws_,
                        float* __restrict__ atom_out)
{
    int i = blockIdx.x * blockDim.x + threadIdx.x;
    const int n4 = NNODES * F / 4;   // 800000 float4s
    if (i < n4) {
        ((float4*)atom_out)[i] = ((const float4*)atom)[i];
    }
    if (i < ZD * NT) {
        int k = i >> 7;          // /128
        int o = i & 127;
        g_wc[i] = (o < 64) ? wf[o * ZD + k] : ws_[(o - 64) * ZD + k];
    }
}

// ---------------------------------------------------------------------------
// K1: message GEMM (64 edges x 128 outs x K=192) + gated activation +
//     gaussian decay + atomicAdd scatter into atom_out.
// Column pairing: thread (tx,ty) computes cols {tx*4+j} (f-part, j<4) and
// {64+tx*4+j} (s-part) so zf/zs pairs live in the same thread.
// ---------------------------------------------------------------------------
__global__ void __launch_bounds__(256)
k1_msg(const float* __restrict__ atom,
       const int*   __restrict__ eidx,   // [2][NE]: row0=src, row1=dst
       const float* __restrict__ efea,   // [NE][64]
       const float* __restrict__ dist,   // [NE]
       const float* __restrict__ bf,     // [64]
       const float* __restrict__ bs,     // [64]
       float* __restrict__ atom_out)
{
    extern __shared__ float sm[];
    float* ws   = sm;                          // 192*128 = 24576 floats
    float* zr   = ws + ZD * NT;                // 64*196  = 12544 floats
    float* sbf  = zr + MT * ZR_STRIDE;         // 128 (bf || bs)
    float* sdec = sbf + NT;                    // 64
    int*   sdst = (int*)(sdec + MT);           // 64
    int*   ssrc = sdst + MT;                   // 64

    const int tid = threadIdx.x;
    const int e0  = blockIdx.x * MT;

    // --- load combined weights from g_wc (fully coalesced, conflict-free) ---
    {
        const float4* wg4 = (const float4*)g_wc;
        float4* ws4 = (float4*)ws;
        #pragma unroll
        for (int i = 0; i < 24; i++)           // 24*256 = 6144 float4
            ws4[tid + i * 256] = wg4[tid + i * 256];
    }
    // --- biases ---
    if (tid < 64)       sbf[tid] = bf[tid];
    else if (tid < 128) sbf[tid] = bs[tid - 64];
    // --- indices + gaussian decay ---
    if (tid < MT) {
        int e = e0 + tid;
        ssrc[tid] = eidx[e];
        sdst[tid] = eidx[NE + e];
        float d = dist[e];
        sdec[tid] = __expf(-d * d * (1.0f / 18.0f));
    }
    __syncthreads();

    // --- gather z rows into shared: z[e] = [atom[dst] | atom[src] | efea[e]]
    // 64 edges * 48 float4 = 3072 float4; 12 per thread, coalesced per edge row
    #pragma unroll
    for (int r = 0; r < 12; r++) {
        int idx = tid + r * 256;               // < 3072
        int el  = idx / 48;                    // local edge
        int k4  = idx % 48;                    // float4 index within z row
        float4 v;
        if (k4 < 16) {
            v = ((const float4*)(atom + (size_t)sdst[el] * F))[k4];
        } else if (k4 < 32) {
            v = ((const float4*)(atom + (size_t)ssrc[el] * F))[k4 - 16];
        } else {
            v = ((const float4*)(efea + (size_t)(e0 + el) * F))[k4 - 32];
        }
        *((float4*)(zr + el * ZR_STRIDE) + k4) = v;
    }
    __syncthreads();

    // --- GEMM mainloop ---
    const int tx = tid & 15;       // 16 col-groups
    const int ty = tid >> 4;       // 16 row-groups
    float acc[4][8];
    #pragma unroll
    for (int i = 0; i < 4; i++)
        #pragma unroll
        for (int j = 0; j < 8; j++) acc[i][j] = 0.0f;

    const float* zbase = zr + ty * 4 * ZR_STRIDE;
    const int cb = tx * 4;

    #pragma unroll 4
    for (int k = 0; k < ZD; k++) {
        float4 b0 = *(const float4*)&ws[k * NT + cb];        // f-part cols
        float4 b1 = *(const float4*)&ws[k * NT + 64 + cb];   // s-part cols
        float a0 = zbase[0 * ZR_STRIDE + k];
        float a1 = zbase[1 * ZR_STRIDE + k];
        float a2 = zbase[2 * ZR_STRIDE + k];
        float a3 = zbase[3 * ZR_STRIDE + k];
        acc[0][0] += a0 * b0.x; acc[0][1] += a0 * b0.y; acc[0][2] += a0 * b0.z; acc[0][3] += a0 * b0.w;
        acc[0][4] += a0 * b1.x; acc[0][5] += a0 * b1.y; acc[0][6] += a0 * b1.z; acc[0][7] += a0 * b1.w;
        acc[1][0] += a1 * b0.x; acc[1][1] += a1 * b0.y; acc[1][2] += a1 * b0.z; acc[1][3] += a1 * b0.w;
        acc[1][4] += a1 * b1.x; acc[1][5] += a1 * b1.y; acc[1][6] += a1 * b1.z; acc[1][7] += a1 * b1.w;
        acc[2][0] += a2 * b0.x; acc[2][1] += a2 * b0.y; acc[2][2] += a2 * b0.z; acc[2][3] += a2 * b0.w;
        acc[2][4] += a2 * b1.x; acc[2][5] += a2 * b1.y; acc[2][6] += a2 * b1.z; acc[2][7] += a2 * b1.w;
        acc[3][0] += a3 * b0.x; acc[3][1] += a3 * b0.y; acc[3][2] += a3 * b0.z; acc[3][3] += a3 * b0.w;
        acc[3][4] += a3 * b1.x; acc[3][5] += a3 * b1.y; acc[3][6] += a3 * b1.z; acc[3][7] += a3 * b1.w;
    }

    // --- epilogue: gated activation, decay, scatter-add ---
    #pragma unroll
    for (int i = 0; i < 4; i++) {
        int r    = ty * 4 + i;
        int dstn = sdst[r];
        float dec = sdec[r];
        float* outrow = atom_out + (size_t)dstn * F;
        #pragma unroll
        for (int j = 0; j < 4; j++) {
            int c = cb + j;
            float zf = acc[i][j]     + sbf[c];
            float zs = acc[i][j + 4] + sbf[64 + c];
            float sig = __fdividef(1.0f, 1.0f + __expf(-zf));
            float sp  = (zs > 15.0f) ? zs : log1pf(__expf(zs));
            atomicAdd(outrow + c, sig * sp * dec);
        }
    }
}

// ---------------------------------------------------------------------------
// K2: edge-update MLP. One warp per edge; fc1 weights register-resident
// (lane owns k = lane + 32t), butterfly-reduce 14 hidden sums, silu on
// lanes 0..13, fc2 via shfl broadcast + conflict-free smem.
// z2 = [atom_out[src] | atom_out[dst] | edge_fea]
// ---------------------------------------------------------------------------
__global__ void __launch_bounds__(256, 2)
k2_edge(const float* __restrict__ atom_out,
        const int*   __restrict__ eidx,
        const float* __restrict__ efea,
        const float* __restrict__ w1,   // [14][192]
        const float* __restrict__ b1,   // [14]
        const float* __restrict__ w2,   // [64][14]
        const float* __restrict__ b2,   // [64]
        float* __restrict__ edge_out,
        int nwarps)
{
    __shared__ float s_w2t[HID * 64];   // transposed: [j][o]
    __shared__ float s_b2[64];
    __shared__ float s_b1[16];

    const int tid  = threadIdx.x;
    const int lane = tid & 31;
    const int wid  = tid >> 5;

    for (int i = tid; i < HID * 64; i += 256) {
        int j = i / 64, o = i % 64;
        s_w2t[i] = w2[o * HID + j];
    }
    if (tid < 64) s_b2[tid] = b2[tid];
    if (tid < 16) s_b1[tid] = (tid < HID) ? b1[tid] : 0.0f;
    __syncthreads();

    // register-resident fc1 weights for this lane's k positions
    float w1r[6][HID];
    #pragma unroll
    for (int t = 0; t < 6; t++)
        #pragma unroll
        for (int j = 0; j < HID; j++)
            w1r[t][j] = w1[j * ZD + (lane + 32 * t)];

    const int gw = blockIdx.x * 8 + wid;
    const unsigned full = 0xffffffffu;

    for (int e = gw; e < NE; e += nwarps) {
        int s = eidx[e];
        int d = eidx[NE + e];
        const float* rs = atom_out + (size_t)s * F;
        const float* rd = atom_out + (size_t)d * F;
        const float* re = efea + (size_t)e * F;

        float z[6];
        z[0] = rs[lane];      z[1] = rs[lane + 32];
        z[2] = rd[lane];      z[3] = rd[lane + 32];
        z[4] = re[lane];      z[5] = re[lane + 32];

        float ph[HID];
        #pragma unroll
        for (int j = 0; j < HID; j++) {
            float a = z[0] * w1r[0][j];
            a += z[1] * w1r[1][j];
            a += z[2] * w1r[2][j];
            a += z[3] * w1r[3][j];
            a += z[4] * w1r[4][j];
            a += z[5] * w1r[5][j];
            ph[j] = a;
        }
        // butterfly reduce each hidden sum across the warp
        #pragma unroll
        for (int j = 0; j < HID; j++) {
            #pragma unroll
            for (int off = 16; off > 0; off >>= 1)
                ph[j] += __shfl_xor_sync(full, ph[j], off);
        }
        // lane j (<14) picks its own hidden value, applies bias + silu
        float myh = ph[0];
        #pragma unroll
        for (int j = 1; j < HID; j++)
            if (lane == j) myh = ph[j];
        int bidx = lane < HID ? lane : 0;
        float x  = myh + s_b1[bidx];
        float hs = x * __fdividef(1.0f, 1.0f + __expf(-x));

        // fc2: each lane computes output channels lane and lane+32
        float a0 = s_b2[lane];
        float a1 = s_b2[lane + 32];
        #pragma unroll
        for (int j = 0; j < HID; j++) {
            float hj = __shfl_sync(full, hs, j);
            a0 += hj * s_w2t[j * 64 + lane];
            a1 += hj * s_w2t[j * 64 + lane + 32];
        }
        float o0 = a0 * __fdividef(1.0f, 1.0f + __expf(-a0));
        float o1 = a1 * __fdividef(1.0f, 1.0f + __expf(-a1));
        edge_out[(size_t)e * F + lane]      = o0;
        edge_out[(size_t)e * F + lane + 32] = o1;
    }
}

// ---------------------------------------------------------------------------
// Launch
// Inputs (metadata order):
//  0 atom_fea [50000*64] f32      1 edge_idx [2*800000] i32
//  2 edge_fea [800000*64] f32     3 batch (unused)
//  4 distance [800000] f32        5 edge_vec (unused)
//  6 lin_f_w [64*192]  7 lin_f_b [64]
//  8 lin_s_w [64*192]  9 lin_s_b [64]
// 10 fc1_w [14*192]   11 fc1_b [14]
// 12 fc2_w [64*14]    13 fc2_b [64]
// Output: atom_out [50000*64] then edge_out [800000*64]
// ---------------------------------------------------------------------------
extern "C" void kernel_launch(void* const* d_in, const int* in_sizes, int n_in,
                              void* d_out, int out_size)
{
    const float* atom  = (const float*)d_in[0];
    const int*   eidx  = (const int*)  d_in[1];
    const float* efea  = (const float*)d_in[2];
    const float* dist  = (const float*)d_in[4];
    const float* wf    = (const float*)d_in[6];
    const float* bf    = (const float*)d_in[7];
    const float* wss   = (const float*)d_in[8];
    const float* bs    = (const float*)d_in[9];
    const float* w1    = (const float*)d_in[10];
    const float* b1    = (const float*)d_in[11];
    const float* w2    = (const float*)d_in[12];
    const float* b2    = (const float*)d_in[13];

    float* atom_out = (float*)d_out;
    float* edge_out = atom_out + (size_t)NNODES * F;

    // K0: init atom_out + build combined weights
    k0_prep<<<(NNODES * F / 4 + 255) / 256, 256>>>(atom, wf, wss, atom_out);

    // K1: message GEMM + scatter
    const int smem_k1 = (ZD * NT + MT * ZR_STRIDE + NT + MT) * 4 + MT * 2 * 4;
    cudaFuncSetAttribute(k1_msg, cudaFuncAttributeMaxDynamicSharedMemorySize, smem_k1);
    k1_msg<<<NE / MT, 256, smem_k1>>>(atom, eidx, efea, dist, bf, bs, atom_out);

    // K2: edge MLP
    const int blocks = 296;               // ~2 blocks/SM
    const int nwarps = blocks * 8;
    k2_edge<<<blocks, 256>>>(atom_out, eidx, efea, w1, b1, w2, b2, edge_out, nwarps);
}